// round 6
// baseline (speedup 1.0000x reference)
#include <cuda_runtime.h>

typedef unsigned long long u64;

#define NTHREADS 128

#define SDIM   3
#define LDIM   4
#define IDIM   3
#define TOT    7
#define SUDIM  10
#define HIDL   64
#define HIDB   32
#define DT_F   0.01f

__device__ __forceinline__ u64 pack2(float lo, float hi) {
    u64 r; asm("mov.b64 %0, {%1, %2};" : "=l"(r) : "f"(lo), "f"(hi)); return r;
}
__device__ __forceinline__ void unpack2(u64 v, float& lo, float& hi) {
    asm("mov.b64 {%0, %1}, %2;" : "=f"(lo), "=f"(hi) : "l"(v));
}
__device__ __forceinline__ u64 ffma2(u64 a, u64 b, u64 c) {
    u64 d; asm("fma.rn.f32x2 %0, %1, %2, %3;" : "=l"(d) : "l"(a), "l"(b), "l"(c));
    return d;
}
__device__ __forceinline__ float fast_tanh(float x) {
    float r; asm("tanh.approx.f32 %0, %1;" : "=f"(r) : "f"(x)); return r;
}
__device__ __forceinline__ u64 tanh2(u64 v) {
    float lo, hi; unpack2(v, lo, hi);
    return pack2(fast_tanh(lo), fast_tanh(hi));
}
__device__ __forceinline__ float hsum(u64 v) {
    float lo, hi; unpack2(v, lo, hi); return lo + hi;
}
__device__ __forceinline__ float getlo(u64 v) {
    float lo, hi; unpack2(v, lo, hi); return lo;
}
__device__ __forceinline__ float gethi(u64 v) {
    float lo, hi; unpack2(v, lo, hi); return hi;
}

// ============================================================================
// Kernel A: next_state  (k-pack raw layout, 4 rows/thread, paired W2 accs)
// ============================================================================
#define A_W1K   0      // 64 x 12: [w0..w9, b1, 0]
#define A_W2Q   768    // 64 x 4:  [(W2[0][j],W2[1][j]),(W2[2][j],W2[3][j])]
#define A_WZK   1024   // 7 x 12: [w0..w9, bz, 0]
#define A_PHYS  1120   // 3 x 8: [a0,a1,a2,bm0,bm1,bm2,0,0]
#define A_B2Q   1144   // 4: (b2_0,b2_1),(b2_2,b2_3)
#define A_TOTAL 1148

__global__ void __launch_bounds__(NTHREADS, 5)
state_kernel(const float* __restrict__ state,
             const float* __restrict__ u,
             const float* __restrict__ gA,  const float* __restrict__ gBm,
             const float* __restrict__ gWz, const float* __restrict__ gbz,
             const float* __restrict__ gW1, const float* __restrict__ gb1,
             const float* __restrict__ gW2, const float* __restrict__ gb2,
             float* __restrict__ out_state,
             int T)   // T = B/4
{
    __shared__ __align__(16) float ws[A_TOTAL];

    for (int idx = threadIdx.x; idx < 64 * 12; idx += NTHREADS) {
        int r = idx / 12, c = idx % 12;
        ws[A_W1K + idx] = (c < 10) ? gW1[r * 10 + c] : (c == 10 ? gb1[r] : 0.0f);
    }
    for (int idx = threadIdx.x; idx < 64 * 4; idx += NTHREADS) {
        int j = idx / 4, o = idx % 4;
        ws[A_W2Q + idx] = gW2[o * HIDL + j];
    }
    for (int idx = threadIdx.x; idx < 7 * 12; idx += NTHREADS) {
        int r = idx / 12, c = idx % 12;
        ws[A_WZK + idx] = (c < 10) ? gWz[r * 10 + c] : (c == 10 ? gbz[r] : 0.0f);
    }
    for (int idx = threadIdx.x; idx < 3 * 8; idx += NTHREADS) {
        int r = idx / 8, c = idx % 8;
        float v = 0.0f;
        if (c < 3) v = gA[r * 3 + c];
        else if (c < 6) v = gBm[r * 3 + (c - 3)];
        ws[A_PHYS + idx] = v;
    }
    for (int idx = threadIdx.x; idx < 4; idx += NTHREADS)
        ws[A_B2Q + idx] = gb2[idx];
    __syncthreads();

    int t = blockIdx.x * NTHREADS + threadIdx.x;
    if (t >= T) return;
    int rr[4] = {t, t + T, t + 2 * T, t + 3 * T};

    // su pairs per row: sp[r][k] = (su[2k], su[2k+1])
    u64 sp[4][5];
    #pragma unroll
    for (int r = 0; r < 4; r++) {
        const float* s = state + (size_t)rr[r] * TOT;
        const float* up = u + (size_t)rr[r] * IDIM;
        sp[r][0] = pack2(__ldg(s + 0), __ldg(s + 1));
        sp[r][1] = pack2(__ldg(s + 2), __ldg(s + 3));
        sp[r][2] = pack2(__ldg(s + 4), __ldg(s + 5));
        sp[r][3] = pack2(__ldg(s + 6), __ldg(up + 0));
        sp[r][4] = pack2(__ldg(up + 1), __ldg(up + 2));
    }

    // ---- Phase 1: physics cand + gate rows 0..2 + store ----
    {
        const ulonglong2* ph = (const ulonglong2*)(ws + A_PHYS);
        const ulonglong2* wzr = (const ulonglong2*)(ws + A_WZK);
        u64 pm[4];
        #pragma unroll
        for (int r = 0; r < 4; r++)
            pm[r] = pack2(getlo(sp[r][1]), gethi(sp[r][3]));  // (s2, u0)
        #pragma unroll
        for (int i = 0; i < SDIM; i++) {
            ulonglong2 p0 = ph[i * 2 + 0], p1 = ph[i * 2 + 1];
            ulonglong2 q0 = wzr[i * 3 + 0], q1 = wzr[i * 3 + 1], q2 = wzr[i * 3 + 2];
            #pragma unroll
            for (int r = 0; r < 4; r++) {
                u64 d = ffma2(p1.x, sp[r][4], 0ull);
                d = ffma2(p0.y, pm[r], d);
                d = ffma2(p0.x, sp[r][0], d);
                float si = (i == 0) ? getlo(sp[r][0])
                         : (i == 1) ? gethi(sp[r][0]) : getlo(sp[r][1]);
                float c = fmaf(DT_F, hsum(d), si);
                u64 g = q2.y;
                g = ffma2(q0.x, sp[r][0], g);
                g = ffma2(q0.y, sp[r][1], g);
                g = ffma2(q1.x, sp[r][2], g);
                g = ffma2(q1.y, sp[r][3], g);
                g = ffma2(q2.x, sp[r][4], g);
                float z = fmaf(0.5f, fast_tanh(0.5f * hsum(g)), 0.5f);
                out_state[(size_t)rr[r] * TOT + i] = fmaf(z, c - si, si);
            }
        }
    }

    // ---- Phase 2: latent MLP with paired accumulators ----
    u64 acc01[4], acc23[4];
    {
        const ulonglong2* w1r = (const ulonglong2*)(ws + A_W1K);
        const ulonglong2* w2q = (const ulonglong2*)(ws + A_W2Q);
        u64 b01 = *(const u64*)(ws + A_B2Q + 0);
        u64 b23 = *(const u64*)(ws + A_B2Q + 2);
        #pragma unroll
        for (int r = 0; r < 4; r++) { acc01[r] = b01; acc23[r] = b23; }
        for (int j = 0; j < HIDL; j++) {
            ulonglong2 q0 = w1r[j * 3 + 0], q1 = w1r[j * 3 + 1], q2 = w1r[j * 3 + 2];
            ulonglong2 wq = w2q[j];
            u64 t0 = q2.y, t1 = q2.y, t2 = q2.y, t3 = q2.y;
            t0 = ffma2(q0.x, sp[0][0], t0);  t1 = ffma2(q0.x, sp[1][0], t1);
            t2 = ffma2(q0.x, sp[2][0], t2);  t3 = ffma2(q0.x, sp[3][0], t3);
            t0 = ffma2(q0.y, sp[0][1], t0);  t1 = ffma2(q0.y, sp[1][1], t1);
            t2 = ffma2(q0.y, sp[2][1], t2);  t3 = ffma2(q0.y, sp[3][1], t3);
            t0 = ffma2(q1.x, sp[0][2], t0);  t1 = ffma2(q1.x, sp[1][2], t1);
            t2 = ffma2(q1.x, sp[2][2], t2);  t3 = ffma2(q1.x, sp[3][2], t3);
            t0 = ffma2(q1.y, sp[0][3], t0);  t1 = ffma2(q1.y, sp[1][3], t1);
            t2 = ffma2(q1.y, sp[2][3], t2);  t3 = ffma2(q1.y, sp[3][3], t3);
            t0 = ffma2(q2.x, sp[0][4], t0);  t1 = ffma2(q2.x, sp[1][4], t1);
            t2 = ffma2(q2.x, sp[2][4], t2);  t3 = ffma2(q2.x, sp[3][4], t3);
            float h0 = fast_tanh(hsum(t0));
            float h1 = fast_tanh(hsum(t1));
            float h2 = fast_tanh(hsum(t2));
            float h3 = fast_tanh(hsum(t3));
            u64 hh0 = pack2(h0, h0), hh1 = pack2(h1, h1);
            u64 hh2 = pack2(h2, h2), hh3 = pack2(h3, h3);
            acc01[0] = ffma2(wq.x, hh0, acc01[0]);  acc23[0] = ffma2(wq.y, hh0, acc23[0]);
            acc01[1] = ffma2(wq.x, hh1, acc01[1]);  acc23[1] = ffma2(wq.y, hh1, acc23[1]);
            acc01[2] = ffma2(wq.x, hh2, acc01[2]);  acc23[2] = ffma2(wq.y, hh2, acc23[2]);
            acc01[3] = ffma2(wq.x, hh3, acc01[3]);  acc23[3] = ffma2(wq.y, hh3, acc23[3]);
        }
    }

    // ---- Phase 3: gate rows 3..6 + store ----
    {
        const ulonglong2* wzr = (const ulonglong2*)(ws + A_WZK);
        #pragma unroll
        for (int o = 0; o < LDIM; o++) {
            int i = SDIM + o;
            ulonglong2 q0 = wzr[i * 3 + 0], q1 = wzr[i * 3 + 1], q2 = wzr[i * 3 + 2];
            #pragma unroll
            for (int r = 0; r < 4; r++) {
                float lat = (o == 0) ? gethi(sp[r][1])
                          : (o == 1) ? getlo(sp[r][2])
                          : (o == 2) ? gethi(sp[r][2]) : getlo(sp[r][3]);
                float dot = (o == 0) ? getlo(acc01[r])
                          : (o == 1) ? gethi(acc01[r])
                          : (o == 2) ? getlo(acc23[r]) : gethi(acc23[r]);
                float c = fmaf(DT_F, dot, lat);
                u64 g = q2.y;
                g = ffma2(q0.x, sp[r][0], g);
                g = ffma2(q0.y, sp[r][1], g);
                g = ffma2(q1.x, sp[r][2], g);
                g = ffma2(q1.y, sp[r][3], g);
                g = ffma2(q2.x, sp[r][4], g);
                float z = fmaf(0.5f, fast_tanh(0.5f * hsum(g)), 0.5f);
                out_state[(size_t)rr[r] * TOT + i] = fmaf(z, c - lat, lat);
            }
        }
    }
}

// ============================================================================
// Kernel B: y  (duplicated-pair layout, 8 rows/thread)
// ============================================================================
#define B_WB1D  0      // 96 rows x 16: [6 w-pairs][bb1 pair][wb2 pair]
#define B_CD    1536   // 3 rows x 8:  [C row 3 pairs][(bb2,bb2) pair]
#define B_TOTAL 1560

__global__ void __launch_bounds__(NTHREADS, 5)
y_kernel(const float* __restrict__ state,
         const float* __restrict__ u,
         const float* __restrict__ gC,
         const float* __restrict__ gWb1, const float* __restrict__ gbb1,
         const float* __restrict__ gWb2, const float* __restrict__ gbb2,
         float* __restrict__ out_y,
         int T)   // T = B/8
{
    __shared__ __align__(16) float ws[B_TOTAL];

    for (int idx = threadIdx.x; idx < 96 * 8; idx += NTHREADS) {
        int r = idx / 8, c = idx % 8;
        float v = (c < 6) ? gWb1[r * 6 + c] : (c == 6 ? gbb1[r] : gWb2[r]);
        ws[B_WB1D + r * 16 + 2 * c] = v;
        ws[B_WB1D + r * 16 + 2 * c + 1] = v;
    }
    for (int idx = threadIdx.x; idx < 3 * 4; idx += NTHREADS) {
        int r = idx / 4, c = idx % 4;
        float v = (c < 3) ? gC[r * 3 + c] : gbb2[r];
        ws[B_CD + r * 8 + 2 * c] = v;
        ws[B_CD + r * 8 + 2 * c + 1] = v;
    }
    __syncthreads();

    int t = blockIdx.x * NTHREADS + threadIdx.x;
    if (t >= T) return;
    int ra = t,         rb = t + T,     rc = t + 2 * T, rd = t + 3 * T;
    int re = t + 4 * T, rf = t + 5 * T, rg = t + 6 * T, rh = t + 7 * T;

    // bi[pair][6]: pairs (ra,rb),(rc,rd),(re,rf),(rg,rh)
    u64 bi[4][6];
    {
        int pr0[4] = {ra, rc, re, rg};
        int pr1[4] = {rb, rd, rf, rh};
        #pragma unroll
        for (int p = 0; p < 4; p++) {
            const float* s0 = state + (size_t)pr0[p] * TOT;
            const float* s1 = state + (size_t)pr1[p] * TOT;
            const float* u0 = u + (size_t)pr0[p] * IDIM;
            const float* u1 = u + (size_t)pr1[p] * IDIM;
            #pragma unroll
            for (int i = 0; i < SDIM; i++)
                bi[p][i] = pack2(__ldg(s0 + i), __ldg(s1 + i));
            #pragma unroll
            for (int i = 0; i < IDIM; i++)
                bi[p][SDIM + i] = pack2(__ldg(u0 + i), __ldg(u1 + i));
        }
    }

    const ulonglong2* wbr = (const ulonglong2*)(ws + B_WB1D);
    const ulonglong2* cdp = (const ulonglong2*)(ws + B_CD);

    #pragma unroll
    for (int k = 0; k < SDIM; k++) {
        ulonglong2 c0 = cdp[k * 2 + 0], c1 = cdp[k * 2 + 1];
        u64 res[4];
        #pragma unroll
        for (int p = 0; p < 4; p++) {
            u64 r = c1.y;     // (bb2, bb2)
            r = ffma2(c0.x, bi[p][0], r);
            r = ffma2(c0.y, bi[p][1], r);
            r = ffma2(c1.x, bi[p][2], r);
            res[p] = r;
        }
        for (int j = 0; j < HIDB; j++) {
            int rw = k * HIDB + j;
            ulonglong2 v0 = wbr[rw * 4 + 0], v1 = wbr[rw * 4 + 1];
            ulonglong2 v2 = wbr[rw * 4 + 2], v3 = wbr[rw * 4 + 3];
            u64 t0 = v3.x, t1 = v3.x, t2 = v3.x, t3 = v3.x;
            t0 = ffma2(v0.x, bi[0][0], t0);  t1 = ffma2(v0.x, bi[1][0], t1);
            t2 = ffma2(v0.x, bi[2][0], t2);  t3 = ffma2(v0.x, bi[3][0], t3);
            t0 = ffma2(v0.y, bi[0][1], t0);  t1 = ffma2(v0.y, bi[1][1], t1);
            t2 = ffma2(v0.y, bi[2][1], t2);  t3 = ffma2(v0.y, bi[3][1], t3);
            t0 = ffma2(v1.x, bi[0][2], t0);  t1 = ffma2(v1.x, bi[1][2], t1);
            t2 = ffma2(v1.x, bi[2][2], t2);  t3 = ffma2(v1.x, bi[3][2], t3);
            t0 = ffma2(v1.y, bi[0][3], t0);  t1 = ffma2(v1.y, bi[1][3], t1);
            t2 = ffma2(v1.y, bi[2][3], t2);  t3 = ffma2(v1.y, bi[3][3], t3);
            t0 = ffma2(v2.x, bi[0][4], t0);  t1 = ffma2(v2.x, bi[1][4], t1);
            t2 = ffma2(v2.x, bi[2][4], t2);  t3 = ffma2(v2.x, bi[3][4], t3);
            t0 = ffma2(v2.y, bi[0][5], t0);  t1 = ffma2(v2.y, bi[1][5], t1);
            t2 = ffma2(v2.y, bi[2][5], t2);  t3 = ffma2(v2.y, bi[3][5], t3);
            res[0] = ffma2(v3.y, tanh2(t0), res[0]);
            res[1] = ffma2(v3.y, tanh2(t1), res[1]);
            res[2] = ffma2(v3.y, tanh2(t2), res[2]);
            res[3] = ffma2(v3.y, tanh2(t3), res[3]);
        }
        int pr0[4] = {ra, rc, re, rg};
        int pr1[4] = {rb, rd, rf, rh};
        #pragma unroll
        for (int p = 0; p < 4; p++) {
            float y0, y1; unpack2(res[p], y0, y1);
            out_y[(size_t)pr0[p] * SDIM + k] = y0;
            out_y[(size_t)pr1[p] * SDIM + k] = y1;
        }
    }
}

extern "C" void kernel_launch(void* const* d_in, const int* in_sizes, int n_in,
                              void* d_out, int out_size) {
    const float* state = (const float*)d_in[0];
    const float* u     = (const float*)d_in[1];
    const float* A     = (const float*)d_in[2];
    const float* Bm    = (const float*)d_in[3];
    const float* C     = (const float*)d_in[4];
    const float* Wz    = (const float*)d_in[5];
    const float* bz    = (const float*)d_in[6];
    const float* W1    = (const float*)d_in[7];
    const float* b1    = (const float*)d_in[8];
    const float* W2    = (const float*)d_in[9];
    const float* b2    = (const float*)d_in[10];
    const float* Wb1   = (const float*)d_in[11];
    const float* bb1   = (const float*)d_in[12];
    const float* Wb2   = (const float*)d_in[13];
    const float* bb2   = (const float*)d_in[14];

    int B = in_sizes[0] / TOT;
    float* out       = (float*)d_out;
    float* out_state = out;                      // [B, 7]
    float* out_y     = out + (size_t)B * TOT;    // [B, 3]

    int Ts = B / 4;
    int grid_s = (Ts + NTHREADS - 1) / NTHREADS;
    state_kernel<<<grid_s, NTHREADS>>>(state, u, A, Bm, Wz, bz, W1, b1, W2, b2,
                                       out_state, Ts);

    int Ty = B / 8;
    int grid_y = (Ty + NTHREADS - 1) / NTHREADS;
    y_kernel<<<grid_y, NTHREADS>>>(state, u, C, Wb1, bb1, Wb2, bb2, out_y, Ty);
}

// round 7
// speedup vs baseline: 1.0521x; 1.0521x over previous
#include <cuda_runtime.h>

typedef unsigned long long u64;

#define NTHREADS 128

#define SDIM   3
#define LDIM   4
#define IDIM   3
#define TOT    7
#define SUDIM  10
#define HIDL   64
#define HIDB   32
#define DT_F   0.01f

__device__ __forceinline__ u64 pack2(float lo, float hi) {
    u64 r; asm("mov.b64 %0, {%1, %2};" : "=l"(r) : "f"(lo), "f"(hi)); return r;
}
__device__ __forceinline__ void unpack2(u64 v, float& lo, float& hi) {
    asm("mov.b64 {%0, %1}, %2;" : "=f"(lo), "=f"(hi) : "l"(v));
}
__device__ __forceinline__ u64 ffma2(u64 a, u64 b, u64 c) {
    u64 d; asm("fma.rn.f32x2 %0, %1, %2, %3;" : "=l"(d) : "l"(a), "l"(b), "l"(c));
    return d;
}
__device__ __forceinline__ float fast_tanh(float x) {
    float r; asm("tanh.approx.f32 %0, %1;" : "=f"(r) : "f"(x)); return r;
}
__device__ __forceinline__ u64 tanh2(u64 v) {
    float lo, hi; unpack2(v, lo, hi);
    return pack2(fast_tanh(lo), fast_tanh(hi));
}
__device__ __forceinline__ float hsum(u64 v) {
    float lo, hi; unpack2(v, lo, hi); return lo + hi;
}
__device__ __forceinline__ float getlo(u64 v) {
    float lo, hi; unpack2(v, lo, hi); return lo;
}
__device__ __forceinline__ float gethi(u64 v) {
    float lo, hi; unpack2(v, lo, hi); return hi;
}

// ---- state-path shared layout (floats) ----
#define A_W1K   0      // 64 x 12: [w0..w9, b1, 0]
#define A_W2Q   768    // 64 x 4:  [(W2[0][j],W2[1][j]),(W2[2][j],W2[3][j])]
#define A_WZK   1024   // 7 x 12: [w0..w9, bz, 0]
#define A_PHYS  1120   // 3 x 8: [a0,a1,a2,bm0,bm1,bm2,0,0]
#define A_B2Q   1144   // 4: (b2_0,b2_1),(b2_2,b2_3)

// ---- y-path shared layout (floats) ----
#define B_WB1D  0      // 96 rows x 16: [6 w-pairs][bb1 pair][wb2 pair]
#define B_CD    1536   // 3 rows x 8:  [C row 3 pairs][(bb2,bb2) pair]

#define WS_TOTAL 1560

__global__ void __launch_bounds__(NTHREADS, 5)
fused_kernel(const float* __restrict__ state,
             const float* __restrict__ u,
             const float* __restrict__ gA,  const float* __restrict__ gBm,
             const float* __restrict__ gC,  const float* __restrict__ gWz,
             const float* __restrict__ gbz, const float* __restrict__ gW1,
             const float* __restrict__ gb1, const float* __restrict__ gW2,
             const float* __restrict__ gb2, const float* __restrict__ gWb1,
             const float* __restrict__ gbb1,const float* __restrict__ gWb2,
             const float* __restrict__ gbb2,
             float* __restrict__ out_state,
             float* __restrict__ out_y,
             int T)   // T = B/4 for both paths
{
    __shared__ __align__(16) float ws[WS_TOTAL];

    if ((blockIdx.x & 1) == 0) {
        // ====================================================================
        // STATE path (even blocks): 4 rows/thread, k-pack layout
        // ====================================================================
        for (int idx = threadIdx.x; idx < 64 * 12; idx += NTHREADS) {
            int r = idx / 12, c = idx % 12;
            ws[A_W1K + idx] = (c < 10) ? gW1[r * 10 + c] : (c == 10 ? gb1[r] : 0.0f);
        }
        for (int idx = threadIdx.x; idx < 64 * 4; idx += NTHREADS) {
            int j = idx / 4, o = idx % 4;
            ws[A_W2Q + idx] = gW2[o * HIDL + j];
        }
        for (int idx = threadIdx.x; idx < 7 * 12; idx += NTHREADS) {
            int r = idx / 12, c = idx % 12;
            ws[A_WZK + idx] = (c < 10) ? gWz[r * 10 + c] : (c == 10 ? gbz[r] : 0.0f);
        }
        for (int idx = threadIdx.x; idx < 3 * 8; idx += NTHREADS) {
            int r = idx / 8, c = idx % 8;
            float v = 0.0f;
            if (c < 3) v = gA[r * 3 + c];
            else if (c < 6) v = gBm[r * 3 + (c - 3)];
            ws[A_PHYS + idx] = v;
        }
        for (int idx = threadIdx.x; idx < 4; idx += NTHREADS)
            ws[A_B2Q + idx] = gb2[idx];
        __syncthreads();

        int t = (blockIdx.x >> 1) * NTHREADS + threadIdx.x;
        if (t >= T) return;
        int rr[4] = {t, t + T, t + 2 * T, t + 3 * T};

        u64 sp[4][5];
        #pragma unroll
        for (int r = 0; r < 4; r++) {
            const float* s = state + (size_t)rr[r] * TOT;
            const float* up = u + (size_t)rr[r] * IDIM;
            sp[r][0] = pack2(__ldg(s + 0), __ldg(s + 1));
            sp[r][1] = pack2(__ldg(s + 2), __ldg(s + 3));
            sp[r][2] = pack2(__ldg(s + 4), __ldg(s + 5));
            sp[r][3] = pack2(__ldg(s + 6), __ldg(up + 0));
            sp[r][4] = pack2(__ldg(up + 1), __ldg(up + 2));
        }

        // Phase 1: physics cand + gate rows 0..2 + store
        {
            const ulonglong2* ph = (const ulonglong2*)(ws + A_PHYS);
            const ulonglong2* wzr = (const ulonglong2*)(ws + A_WZK);
            u64 pm[4];
            #pragma unroll
            for (int r = 0; r < 4; r++)
                pm[r] = pack2(getlo(sp[r][1]), gethi(sp[r][3]));  // (s2, u0)
            #pragma unroll
            for (int i = 0; i < SDIM; i++) {
                ulonglong2 p0 = ph[i * 2 + 0], p1 = ph[i * 2 + 1];
                ulonglong2 q0 = wzr[i * 3 + 0], q1 = wzr[i * 3 + 1], q2 = wzr[i * 3 + 2];
                #pragma unroll
                for (int r = 0; r < 4; r++) {
                    u64 d = ffma2(p1.x, sp[r][4], 0ull);
                    d = ffma2(p0.y, pm[r], d);
                    d = ffma2(p0.x, sp[r][0], d);
                    float si = (i == 0) ? getlo(sp[r][0])
                             : (i == 1) ? gethi(sp[r][0]) : getlo(sp[r][1]);
                    float c = fmaf(DT_F, hsum(d), si);
                    u64 g = q2.y;
                    g = ffma2(q0.x, sp[r][0], g);
                    g = ffma2(q0.y, sp[r][1], g);
                    g = ffma2(q1.x, sp[r][2], g);
                    g = ffma2(q1.y, sp[r][3], g);
                    g = ffma2(q2.x, sp[r][4], g);
                    float z = fmaf(0.5f, fast_tanh(0.5f * hsum(g)), 0.5f);
                    out_state[(size_t)rr[r] * TOT + i] = fmaf(z, c - si, si);
                }
            }
        }

        // Phase 2: latent MLP with paired accumulators
        u64 acc01[4], acc23[4];
        {
            const ulonglong2* w1r = (const ulonglong2*)(ws + A_W1K);
            const ulonglong2* w2q = (const ulonglong2*)(ws + A_W2Q);
            u64 b01 = *(const u64*)(ws + A_B2Q + 0);
            u64 b23 = *(const u64*)(ws + A_B2Q + 2);
            #pragma unroll
            for (int r = 0; r < 4; r++) { acc01[r] = b01; acc23[r] = b23; }
            for (int j = 0; j < HIDL; j++) {
                ulonglong2 q0 = w1r[j * 3 + 0], q1 = w1r[j * 3 + 1], q2 = w1r[j * 3 + 2];
                ulonglong2 wq = w2q[j];
                u64 t0 = q2.y, t1 = q2.y, t2 = q2.y, t3 = q2.y;
                t0 = ffma2(q0.x, sp[0][0], t0);  t1 = ffma2(q0.x, sp[1][0], t1);
                t2 = ffma2(q0.x, sp[2][0], t2);  t3 = ffma2(q0.x, sp[3][0], t3);
                t0 = ffma2(q0.y, sp[0][1], t0);  t1 = ffma2(q0.y, sp[1][1], t1);
                t2 = ffma2(q0.y, sp[2][1], t2);  t3 = ffma2(q0.y, sp[3][1], t3);
                t0 = ffma2(q1.x, sp[0][2], t0);  t1 = ffma2(q1.x, sp[1][2], t1);
                t2 = ffma2(q1.x, sp[2][2], t2);  t3 = ffma2(q1.x, sp[3][2], t3);
                t0 = ffma2(q1.y, sp[0][3], t0);  t1 = ffma2(q1.y, sp[1][3], t1);
                t2 = ffma2(q1.y, sp[2][3], t2);  t3 = ffma2(q1.y, sp[3][3], t3);
                t0 = ffma2(q2.x, sp[0][4], t0);  t1 = ffma2(q2.x, sp[1][4], t1);
                t2 = ffma2(q2.x, sp[2][4], t2);  t3 = ffma2(q2.x, sp[3][4], t3);
                float h0 = fast_tanh(hsum(t0));
                float h1 = fast_tanh(hsum(t1));
                float h2 = fast_tanh(hsum(t2));
                float h3 = fast_tanh(hsum(t3));
                u64 hh0 = pack2(h0, h0), hh1 = pack2(h1, h1);
                u64 hh2 = pack2(h2, h2), hh3 = pack2(h3, h3);
                acc01[0] = ffma2(wq.x, hh0, acc01[0]);  acc23[0] = ffma2(wq.y, hh0, acc23[0]);
                acc01[1] = ffma2(wq.x, hh1, acc01[1]);  acc23[1] = ffma2(wq.y, hh1, acc23[1]);
                acc01[2] = ffma2(wq.x, hh2, acc01[2]);  acc23[2] = ffma2(wq.y, hh2, acc23[2]);
                acc01[3] = ffma2(wq.x, hh3, acc01[3]);  acc23[3] = ffma2(wq.y, hh3, acc23[3]);
            }
        }

        // Phase 3: gate rows 3..6 + store
        {
            const ulonglong2* wzr = (const ulonglong2*)(ws + A_WZK);
            #pragma unroll
            for (int o = 0; o < LDIM; o++) {
                int i = SDIM + o;
                ulonglong2 q0 = wzr[i * 3 + 0], q1 = wzr[i * 3 + 1], q2 = wzr[i * 3 + 2];
                #pragma unroll
                for (int r = 0; r < 4; r++) {
                    float lat = (o == 0) ? gethi(sp[r][1])
                              : (o == 1) ? getlo(sp[r][2])
                              : (o == 2) ? gethi(sp[r][2]) : getlo(sp[r][3]);
                    float dot = (o == 0) ? getlo(acc01[r])
                              : (o == 1) ? gethi(acc01[r])
                              : (o == 2) ? getlo(acc23[r]) : gethi(acc23[r]);
                    float c = fmaf(DT_F, dot, lat);
                    u64 g = q2.y;
                    g = ffma2(q0.x, sp[r][0], g);
                    g = ffma2(q0.y, sp[r][1], g);
                    g = ffma2(q1.x, sp[r][2], g);
                    g = ffma2(q1.y, sp[r][3], g);
                    g = ffma2(q2.x, sp[r][4], g);
                    float z = fmaf(0.5f, fast_tanh(0.5f * hsum(g)), 0.5f);
                    out_state[(size_t)rr[r] * TOT + i] = fmaf(z, c - lat, lat);
                }
            }
        }
    } else {
        // ====================================================================
        // Y path (odd blocks): 4 rows/thread, duplicated-pair layout
        // ====================================================================
        for (int idx = threadIdx.x; idx < 96 * 8; idx += NTHREADS) {
            int r = idx / 8, c = idx % 8;
            float v = (c < 6) ? gWb1[r * 6 + c] : (c == 6 ? gbb1[r] : gWb2[r]);
            ws[B_WB1D + r * 16 + 2 * c] = v;
            ws[B_WB1D + r * 16 + 2 * c + 1] = v;
        }
        for (int idx = threadIdx.x; idx < 3 * 4; idx += NTHREADS) {
            int r = idx / 4, c = idx % 4;
            float v = (c < 3) ? gC[r * 3 + c] : gbb2[r];
            ws[B_CD + r * 8 + 2 * c] = v;
            ws[B_CD + r * 8 + 2 * c + 1] = v;
        }
        __syncthreads();

        int t = (blockIdx.x >> 1) * NTHREADS + threadIdx.x;
        if (t >= T) return;
        int r0 = t, r1 = t + T, r2 = t + 2 * T, r3 = t + 3 * T;

        u64 biA[6], biB[6];
        #pragma unroll
        for (int i = 0; i < SDIM; i++) {
            biA[i] = pack2(__ldg(state + (size_t)r0 * TOT + i),
                           __ldg(state + (size_t)r1 * TOT + i));
            biB[i] = pack2(__ldg(state + (size_t)r2 * TOT + i),
                           __ldg(state + (size_t)r3 * TOT + i));
        }
        #pragma unroll
        for (int i = 0; i < IDIM; i++) {
            biA[SDIM + i] = pack2(__ldg(u + (size_t)r0 * IDIM + i),
                                  __ldg(u + (size_t)r1 * IDIM + i));
            biB[SDIM + i] = pack2(__ldg(u + (size_t)r2 * IDIM + i),
                                  __ldg(u + (size_t)r3 * IDIM + i));
        }

        const ulonglong2* wbr = (const ulonglong2*)(ws + B_WB1D);
        const ulonglong2* cdp = (const ulonglong2*)(ws + B_CD);

        #pragma unroll
        for (int k = 0; k < SDIM; k++) {
            ulonglong2 c0 = cdp[k * 2 + 0], c1 = cdp[k * 2 + 1];
            u64 resA = c1.y, resB = c1.y;       // start from (bb2, bb2)
            resA = ffma2(c0.x, biA[0], resA);  resB = ffma2(c0.x, biB[0], resB);
            resA = ffma2(c0.y, biA[1], resA);  resB = ffma2(c0.y, biB[1], resB);
            resA = ffma2(c1.x, biA[2], resA);  resB = ffma2(c1.x, biB[2], resB);
            #pragma unroll 4
            for (int j = 0; j < HIDB; j++) {
                int r = k * HIDB + j;
                ulonglong2 v0 = wbr[r * 4 + 0], v1 = wbr[r * 4 + 1];
                ulonglong2 v2 = wbr[r * 4 + 2], v3 = wbr[r * 4 + 3];
                u64 tA = v3.x, tB = v3.x;
                tA = ffma2(v0.x, biA[0], tA);  tB = ffma2(v0.x, biB[0], tB);
                tA = ffma2(v0.y, biA[1], tA);  tB = ffma2(v0.y, biB[1], tB);
                tA = ffma2(v1.x, biA[2], tA);  tB = ffma2(v1.x, biB[2], tB);
                tA = ffma2(v1.y, biA[3], tA);  tB = ffma2(v1.y, biB[3], tB);
                tA = ffma2(v2.x, biA[4], tA);  tB = ffma2(v2.x, biB[4], tB);
                tA = ffma2(v2.y, biA[5], tA);  tB = ffma2(v2.y, biB[5], tB);
                resA = ffma2(v3.y, tanh2(tA), resA);
                resB = ffma2(v3.y, tanh2(tB), resB);
            }
            float y0, y1, y2, y3;
            unpack2(resA, y0, y1);  unpack2(resB, y2, y3);
            out_y[(size_t)r0 * SDIM + k] = y0;
            out_y[(size_t)r1 * SDIM + k] = y1;
            out_y[(size_t)r2 * SDIM + k] = y2;
            out_y[(size_t)r3 * SDIM + k] = y3;
        }
    }
}

extern "C" void kernel_launch(void* const* d_in, const int* in_sizes, int n_in,
                              void* d_out, int out_size) {
    const float* state = (const float*)d_in[0];
    const float* u     = (const float*)d_in[1];
    const float* A     = (const float*)d_in[2];
    const float* Bm    = (const float*)d_in[3];
    const float* C     = (const float*)d_in[4];
    const float* Wz    = (const float*)d_in[5];
    const float* bz    = (const float*)d_in[6];
    const float* W1    = (const float*)d_in[7];
    const float* b1    = (const float*)d_in[8];
    const float* W2    = (const float*)d_in[9];
    const float* b2    = (const float*)d_in[10];
    const float* Wb1   = (const float*)d_in[11];
    const float* bb1   = (const float*)d_in[12];
    const float* Wb2   = (const float*)d_in[13];
    const float* bb2   = (const float*)d_in[14];

    int B = in_sizes[0] / TOT;
    float* out       = (float*)d_out;
    float* out_state = out;                      // [B, 7]
    float* out_y     = out + (size_t)B * TOT;    // [B, 3]

    int T = B / 4;                               // rows per group, both paths
    int blocks_per_path = (T + NTHREADS - 1) / NTHREADS;
    int grid = blocks_per_path * 2;              // even = state, odd = y

    fused_kernel<<<grid, NTHREADS>>>(state, u, A, Bm, C, Wz, bz, W1, b1,
                                     W2, b2, Wb1, bb1, Wb2, bb2,
                                     out_state, out_y, T);
}

// round 8
// speedup vs baseline: 1.1290x; 1.0731x over previous
#include <cuda_runtime.h>

typedef unsigned long long u64;

#define NTHREADS 128

#define SDIM   3
#define LDIM   4
#define IDIM   3
#define TOT    7
#define SUDIM  10
#define HIDL   64
#define HIDB   32
#define DT_F   0.01f

// ---- constant-memory layout (float offsets; all pair bases even) ----
#define CW1   0      // 64 x 12: [w0..w9, b1, 0]
#define CW2Q  768    // 64 x 4:  [W2[0][j],W2[1][j],W2[2][j],W2[3][j]]
#define CWZ   1024   // 7 x 12:  [w0..w9, bz, 0]
#define CPHYS 1108   // 3 x 8:   [a0,a1,a2,bm0,bm1,bm2,0,0]
#define CB2   1132   // 4:       b2
#define CWB   1136   // 96 x 8:  [w0..w5, bb1, wb2]
#define CCD   1904   // 3 x 4:   [c0,c1,c2,bb2]
#define CW_TOTAL 1916

__constant__ float cw[CW_TOTAL];
__device__ float g_stage[CW_TOTAL];

__device__ __forceinline__ u64 pack2(float lo, float hi) {
    u64 r; asm("mov.b64 %0, {%1, %2};" : "=l"(r) : "f"(lo), "f"(hi)); return r;
}
__device__ __forceinline__ void unpack2(u64 v, float& lo, float& hi) {
    asm("mov.b64 {%0, %1}, %2;" : "=f"(lo), "=f"(hi) : "l"(v));
}
__device__ __forceinline__ u64 ffma2(u64 a, u64 b, u64 c) {
    u64 d; asm("fma.rn.f32x2 %0, %1, %2, %3;" : "=l"(d) : "l"(a), "l"(b), "l"(c));
    return d;
}
__device__ __forceinline__ float fast_tanh(float x) {
    float r; asm("tanh.approx.f32 %0, %1;" : "=f"(r) : "f"(x)); return r;
}
__device__ __forceinline__ float hsum(u64 v) {
    float lo, hi; unpack2(v, lo, hi); return lo + hi;
}
__device__ __forceinline__ float getlo(u64 v) {
    float lo, hi; unpack2(v, lo, hi); return lo;
}
__device__ __forceinline__ float gethi(u64 v) {
    float lo, hi; unpack2(v, lo, hi); return hi;
}
#define CPAIR(off) (*(const u64*)(cw + (off)))

// ============================================================================
// Pack kernel: rearrange raw weights into g_stage (then memcpy -> cw)
// ============================================================================
__global__ void pack_weights(const float* __restrict__ gA,  const float* __restrict__ gBm,
                             const float* __restrict__ gC,  const float* __restrict__ gWz,
                             const float* __restrict__ gbz, const float* __restrict__ gW1,
                             const float* __restrict__ gb1, const float* __restrict__ gW2,
                             const float* __restrict__ gb2, const float* __restrict__ gWb1,
                             const float* __restrict__ gbb1,const float* __restrict__ gWb2,
                             const float* __restrict__ gbb2)
{
    int tid = blockIdx.x * blockDim.x + threadIdx.x;
    int nt = gridDim.x * blockDim.x;
    for (int idx = tid; idx < 64 * 12; idx += nt) {
        int r = idx / 12, c = idx % 12;
        g_stage[CW1 + idx] = (c < 10) ? gW1[r * 10 + c] : (c == 10 ? gb1[r] : 0.0f);
    }
    for (int idx = tid; idx < 64 * 4; idx += nt) {
        int j = idx / 4, o = idx % 4;
        g_stage[CW2Q + idx] = gW2[o * HIDL + j];
    }
    for (int idx = tid; idx < 7 * 12; idx += nt) {
        int r = idx / 12, c = idx % 12;
        g_stage[CWZ + idx] = (c < 10) ? gWz[r * 10 + c] : (c == 10 ? gbz[r] : 0.0f);
    }
    for (int idx = tid; idx < 3 * 8; idx += nt) {
        int r = idx / 8, c = idx % 8;
        float v = 0.0f;
        if (c < 3) v = gA[r * 3 + c];
        else if (c < 6) v = gBm[r * 3 + (c - 3)];
        g_stage[CPHYS + idx] = v;
    }
    for (int idx = tid; idx < 4; idx += nt)
        g_stage[CB2 + idx] = gb2[idx];
    for (int idx = tid; idx < 96 * 8; idx += nt) {
        int r = idx / 8, c = idx % 8;
        g_stage[CWB + idx] = (c < 6) ? gWb1[r * 6 + c] : (c == 6 ? gbb1[r] : gWb2[r]);
    }
    for (int idx = tid; idx < 3 * 4; idx += nt) {
        int r = idx / 4, c = idx % 4;
        g_stage[CCD + idx] = (c < 3) ? gC[r * 3 + c] : gbb2[r];
    }
}

// ============================================================================
// Fused compute kernel: even blocks -> next_state, odd blocks -> y
// ============================================================================
__global__ void __launch_bounds__(NTHREADS, 6)
fused_kernel(const float* __restrict__ state,
             const float* __restrict__ u,
             float* __restrict__ out_state,
             float* __restrict__ out_y,
             int T)   // T = B/4 for both paths
{
    if ((blockIdx.x & 1) == 0) {
        // ====================================================================
        // STATE path: 4 rows/thread
        // ====================================================================
        int t = (blockIdx.x >> 1) * NTHREADS + threadIdx.x;
        if (t >= T) return;
        int rr[4] = {t, t + T, t + 2 * T, t + 3 * T};

        u64 sp[4][5];
        #pragma unroll
        for (int r = 0; r < 4; r++) {
            const float* s = state + (size_t)rr[r] * TOT;
            const float* up = u + (size_t)rr[r] * IDIM;
            sp[r][0] = pack2(__ldg(s + 0), __ldg(s + 1));
            sp[r][1] = pack2(__ldg(s + 2), __ldg(s + 3));
            sp[r][2] = pack2(__ldg(s + 4), __ldg(s + 5));
            sp[r][3] = pack2(__ldg(s + 6), __ldg(up + 0));
            sp[r][4] = pack2(__ldg(up + 1), __ldg(up + 2));
        }

        // Phase 1: physics cand + gate rows 0..2 + store
        {
            u64 pm[4];
            #pragma unroll
            for (int r = 0; r < 4; r++)
                pm[r] = pack2(getlo(sp[r][1]), gethi(sp[r][3]));  // (s2, u0)
            #pragma unroll
            for (int i = 0; i < SDIM; i++) {
                u64 p0 = CPAIR(CPHYS + i * 8 + 0);
                u64 p1 = CPAIR(CPHYS + i * 8 + 2);
                u64 p2 = CPAIR(CPHYS + i * 8 + 4);
                u64 q0 = CPAIR(CWZ + i * 12 + 0);
                u64 q1 = CPAIR(CWZ + i * 12 + 2);
                u64 q2 = CPAIR(CWZ + i * 12 + 4);
                u64 q3 = CPAIR(CWZ + i * 12 + 6);
                u64 q4 = CPAIR(CWZ + i * 12 + 8);
                u64 qb = CPAIR(CWZ + i * 12 + 10);  // (bz, 0)
                #pragma unroll
                for (int r = 0; r < 4; r++) {
                    u64 d = ffma2(p2, sp[r][4], 0ull);
                    d = ffma2(p1, pm[r], d);
                    d = ffma2(p0, sp[r][0], d);
                    float si = (i == 0) ? getlo(sp[r][0])
                             : (i == 1) ? gethi(sp[r][0]) : getlo(sp[r][1]);
                    float c = fmaf(DT_F, hsum(d), si);
                    u64 g = qb;
                    g = ffma2(q0, sp[r][0], g);
                    g = ffma2(q1, sp[r][1], g);
                    g = ffma2(q2, sp[r][2], g);
                    g = ffma2(q3, sp[r][3], g);
                    g = ffma2(q4, sp[r][4], g);
                    float z = fmaf(0.5f, fast_tanh(0.5f * hsum(g)), 0.5f);
                    out_state[(size_t)rr[r] * TOT + i] = fmaf(z, c - si, si);
                }
            }
        }

        // Phase 2: latent MLP with paired accumulators
        u64 acc01[4], acc23[4];
        {
            u64 b01 = CPAIR(CB2 + 0);
            u64 b23 = CPAIR(CB2 + 2);
            #pragma unroll
            for (int r = 0; r < 4; r++) { acc01[r] = b01; acc23[r] = b23; }
            #pragma unroll 4
            for (int j = 0; j < HIDL; j++) {
                u64 q0 = CPAIR(CW1 + j * 12 + 0);
                u64 q1 = CPAIR(CW1 + j * 12 + 2);
                u64 q2 = CPAIR(CW1 + j * 12 + 4);
                u64 q3 = CPAIR(CW1 + j * 12 + 6);
                u64 q4 = CPAIR(CW1 + j * 12 + 8);
                u64 qb = CPAIR(CW1 + j * 12 + 10);  // (b1, 0)
                u64 w01 = CPAIR(CW2Q + j * 4 + 0);
                u64 w23 = CPAIR(CW2Q + j * 4 + 2);
                u64 t0 = qb, t1 = qb, t2 = qb, t3 = qb;
                t0 = ffma2(q0, sp[0][0], t0);  t1 = ffma2(q0, sp[1][0], t1);
                t2 = ffma2(q0, sp[2][0], t2);  t3 = ffma2(q0, sp[3][0], t3);
                t0 = ffma2(q1, sp[0][1], t0);  t1 = ffma2(q1, sp[1][1], t1);
                t2 = ffma2(q1, sp[2][1], t2);  t3 = ffma2(q1, sp[3][1], t3);
                t0 = ffma2(q2, sp[0][2], t0);  t1 = ffma2(q2, sp[1][2], t1);
                t2 = ffma2(q2, sp[2][2], t2);  t3 = ffma2(q2, sp[3][2], t3);
                t0 = ffma2(q3, sp[0][3], t0);  t1 = ffma2(q3, sp[1][3], t1);
                t2 = ffma2(q3, sp[2][3], t2);  t3 = ffma2(q3, sp[3][3], t3);
                t0 = ffma2(q4, sp[0][4], t0);  t1 = ffma2(q4, sp[1][4], t1);
                t2 = ffma2(q4, sp[2][4], t2);  t3 = ffma2(q4, sp[3][4], t3);
                float h0 = fast_tanh(hsum(t0));
                float h1 = fast_tanh(hsum(t1));
                float h2 = fast_tanh(hsum(t2));
                float h3 = fast_tanh(hsum(t3));
                u64 hh0 = pack2(h0, h0), hh1 = pack2(h1, h1);
                u64 hh2 = pack2(h2, h2), hh3 = pack2(h3, h3);
                acc01[0] = ffma2(w01, hh0, acc01[0]);  acc23[0] = ffma2(w23, hh0, acc23[0]);
                acc01[1] = ffma2(w01, hh1, acc01[1]);  acc23[1] = ffma2(w23, hh1, acc23[1]);
                acc01[2] = ffma2(w01, hh2, acc01[2]);  acc23[2] = ffma2(w23, hh2, acc23[2]);
                acc01[3] = ffma2(w01, hh3, acc01[3]);  acc23[3] = ffma2(w23, hh3, acc23[3]);
            }
        }

        // Phase 3: gate rows 3..6 + store
        {
            #pragma unroll
            for (int o = 0; o < LDIM; o++) {
                int i = SDIM + o;
                u64 q0 = CPAIR(CWZ + i * 12 + 0);
                u64 q1 = CPAIR(CWZ + i * 12 + 2);
                u64 q2 = CPAIR(CWZ + i * 12 + 4);
                u64 q3 = CPAIR(CWZ + i * 12 + 6);
                u64 q4 = CPAIR(CWZ + i * 12 + 8);
                u64 qb = CPAIR(CWZ + i * 12 + 10);
                #pragma unroll
                for (int r = 0; r < 4; r++) {
                    float lat = (o == 0) ? gethi(sp[r][1])
                              : (o == 1) ? getlo(sp[r][2])
                              : (o == 2) ? gethi(sp[r][2]) : getlo(sp[r][3]);
                    float dot = (o == 0) ? getlo(acc01[r])
                              : (o == 1) ? gethi(acc01[r])
                              : (o == 2) ? getlo(acc23[r]) : gethi(acc23[r]);
                    float c = fmaf(DT_F, dot, lat);
                    u64 g = qb;
                    g = ffma2(q0, sp[r][0], g);
                    g = ffma2(q1, sp[r][1], g);
                    g = ffma2(q2, sp[r][2], g);
                    g = ffma2(q3, sp[r][3], g);
                    g = ffma2(q4, sp[r][4], g);
                    float z = fmaf(0.5f, fast_tanh(0.5f * hsum(g)), 0.5f);
                    out_state[(size_t)rr[r] * TOT + i] = fmaf(z, c - lat, lat);
                }
            }
        }
    } else {
        // ====================================================================
        // Y path: 4 rows/thread, within-row pairing
        // ====================================================================
        int t = (blockIdx.x >> 1) * NTHREADS + threadIdx.x;
        if (t >= T) return;
        int rr[4] = {t, t + T, t + 2 * T, t + 3 * T};

        // bp[r]: (s0,s1), (s2,u0), (u1,u2)
        u64 bp[4][3];
        u64 s2one[4];
        #pragma unroll
        for (int r = 0; r < 4; r++) {
            const float* s = state + (size_t)rr[r] * TOT;
            const float* up = u + (size_t)rr[r] * IDIM;
            bp[r][0] = pack2(__ldg(s + 0), __ldg(s + 1));
            bp[r][1] = pack2(__ldg(s + 2), __ldg(up + 0));
            bp[r][2] = pack2(__ldg(up + 1), __ldg(up + 2));
            s2one[r] = pack2(getlo(bp[r][1]), 1.0f);   // (s2, 1)
        }

        #pragma unroll
        for (int k = 0; k < SDIM; k++) {
            u64 cp0 = CPAIR(CCD + k * 4 + 0);   // (c0, c1)
            u64 cp1 = CPAIR(CCD + k * 4 + 2);   // (c2, bb2)
            float res[4];
            #pragma unroll
            for (int r = 0; r < 4; r++)
                res[r] = hsum(ffma2(cp1, s2one[r], ffma2(cp0, bp[r][0], 0ull)));
            #pragma unroll 4
            for (int j = 0; j < HIDB; j++) {
                int row = k * HIDB + j;
                u64 w01 = CPAIR(CWB + row * 8 + 0);
                u64 w23 = CPAIR(CWB + row * 8 + 2);
                u64 w45 = CPAIR(CWB + row * 8 + 4);
                u64 bwp = CPAIR(CWB + row * 8 + 6);   // (bb1, wb2)
                u64 tinit = pack2(getlo(bwp), 0.0f);
                float wb2 = gethi(bwp);
                u64 t0 = ffma2(w01, bp[0][0], tinit);
                u64 t1 = ffma2(w01, bp[1][0], tinit);
                u64 t2 = ffma2(w01, bp[2][0], tinit);
                u64 t3 = ffma2(w01, bp[3][0], tinit);
                t0 = ffma2(w23, bp[0][1], t0);
                t1 = ffma2(w23, bp[1][1], t1);
                t2 = ffma2(w23, bp[2][1], t2);
                t3 = ffma2(w23, bp[3][1], t3);
                t0 = ffma2(w45, bp[0][2], t0);
                t1 = ffma2(w45, bp[1][2], t1);
                t2 = ffma2(w45, bp[2][2], t2);
                t3 = ffma2(w45, bp[3][2], t3);
                res[0] = fmaf(wb2, fast_tanh(hsum(t0)), res[0]);
                res[1] = fmaf(wb2, fast_tanh(hsum(t1)), res[1]);
                res[2] = fmaf(wb2, fast_tanh(hsum(t2)), res[2]);
                res[3] = fmaf(wb2, fast_tanh(hsum(t3)), res[3]);
            }
            #pragma unroll
            for (int r = 0; r < 4; r++)
                out_y[(size_t)rr[r] * SDIM + k] = res[r];
        }
    }
}

extern "C" void kernel_launch(void* const* d_in, const int* in_sizes, int n_in,
                              void* d_out, int out_size) {
    const float* state = (const float*)d_in[0];
    const float* u     = (const float*)d_in[1];
    const float* A     = (const float*)d_in[2];
    const float* Bm    = (const float*)d_in[3];
    const float* C     = (const float*)d_in[4];
    const float* Wz    = (const float*)d_in[5];
    const float* bz    = (const float*)d_in[6];
    const float* W1    = (const float*)d_in[7];
    const float* b1    = (const float*)d_in[8];
    const float* W2    = (const float*)d_in[9];
    const float* b2    = (const float*)d_in[10];
    const float* Wb1   = (const float*)d_in[11];
    const float* bb1   = (const float*)d_in[12];
    const float* Wb2   = (const float*)d_in[13];
    const float* bb2   = (const float*)d_in[14];

    int B = in_sizes[0] / TOT;
    float* out       = (float*)d_out;
    float* out_state = out;                      // [B, 7]
    float* out_y     = out + (size_t)B * TOT;    // [B, 3]

    // 1) pack weights into staging, 2) memcpy D2D into __constant__
    pack_weights<<<8, 256>>>(A, Bm, C, Wz, bz, W1, b1, W2, b2,
                             Wb1, bb1, Wb2, bb2);
    void* cw_addr = nullptr;
    void* st_addr = nullptr;
    cudaGetSymbolAddress(&cw_addr, cw);
    cudaGetSymbolAddress(&st_addr, g_stage);
    cudaMemcpyAsync(cw_addr, st_addr, CW_TOTAL * sizeof(float),
                    cudaMemcpyDeviceToDevice);

    // 3) fused compute
    int T = B / 4;
    int blocks_per_path = (T + NTHREADS - 1) / NTHREADS;
    int grid = blocks_per_path * 2;
    fused_kernel<<<grid, NTHREADS>>>(state, u, out_state, out_y, T);
}

// round 9
// speedup vs baseline: 1.1311x; 1.0018x over previous
#include <cuda_runtime.h>

typedef unsigned long long u64;

#define NTHREADS 128

#define SDIM   3
#define LDIM   4
#define IDIM   3
#define TOT    7
#define SUDIM  10
#define HIDL   64
#define HIDB   32
#define DT_F   0.01f

// ---- constant-memory layout (float offsets; all rows 16B-aligned) ----
#define CW1   0      // 64 x 12: [w0..w9, b1, 0]
#define CW2Q  768    // 64 x 4:  [W2[0][j],W2[1][j],W2[2][j],W2[3][j]]
#define CWZ   1024   // 7 x 12:  [w0..w9, bz, 0]
#define CPHYS 1108   // 3 x 8:   [a0,a1,a2,bm0,bm1,bm2,0,0]
#define CB2   1132   // 4:       b2
#define CWB   1136   // 96 x 8:  [w0..w5, bb1, wb2]
#define CCD   1904   // 3 x 4:   [c0,c1,c2,bb2]
#define CW_TOTAL 1916

__constant__ __align__(16) float cw[CW_TOTAL];
__device__ __align__(16) float g_stage[CW_TOTAL];

__device__ __forceinline__ u64 pack2(float lo, float hi) {
    u64 r; asm("mov.b64 %0, {%1, %2};" : "=l"(r) : "f"(lo), "f"(hi)); return r;
}
__device__ __forceinline__ void unpack2(u64 v, float& lo, float& hi) {
    asm("mov.b64 {%0, %1}, %2;" : "=f"(lo), "=f"(hi) : "l"(v));
}
__device__ __forceinline__ u64 ffma2(u64 a, u64 b, u64 c) {
    u64 d; asm("fma.rn.f32x2 %0, %1, %2, %3;" : "=l"(d) : "l"(a), "l"(b), "l"(c));
    return d;
}
__device__ __forceinline__ float fast_tanh(float x) {
    float r; asm("tanh.approx.f32 %0, %1;" : "=f"(r) : "f"(x)); return r;
}
__device__ __forceinline__ float hsum(u64 v) {
    float lo, hi; unpack2(v, lo, hi); return lo + hi;
}
__device__ __forceinline__ float getlo(u64 v) {
    float lo, hi; unpack2(v, lo, hi); return lo;
}
__device__ __forceinline__ float gethi(u64 v) {
    float lo, hi; unpack2(v, lo, hi); return hi;
}
// One LDC.128: four consecutive floats as two f32x2 pairs
#define CQUAD(off) (*(const ulonglong2*)(cw + (off)))

// ============================================================================
// Pack kernel: rearrange raw weights into g_stage (then memcpy -> cw)
// ============================================================================
__global__ void pack_weights(const float* __restrict__ gA,  const float* __restrict__ gBm,
                             const float* __restrict__ gC,  const float* __restrict__ gWz,
                             const float* __restrict__ gbz, const float* __restrict__ gW1,
                             const float* __restrict__ gb1, const float* __restrict__ gW2,
                             const float* __restrict__ gb2, const float* __restrict__ gWb1,
                             const float* __restrict__ gbb1,const float* __restrict__ gWb2,
                             const float* __restrict__ gbb2)
{
    int tid = blockIdx.x * blockDim.x + threadIdx.x;
    int nt = gridDim.x * blockDim.x;
    for (int idx = tid; idx < 64 * 12; idx += nt) {
        int r = idx / 12, c = idx % 12;
        g_stage[CW1 + idx] = (c < 10) ? gW1[r * 10 + c] : (c == 10 ? gb1[r] : 0.0f);
    }
    for (int idx = tid; idx < 64 * 4; idx += nt) {
        int j = idx / 4, o = idx % 4;
        g_stage[CW2Q + idx] = gW2[o * HIDL + j];
    }
    for (int idx = tid; idx < 7 * 12; idx += nt) {
        int r = idx / 12, c = idx % 12;
        g_stage[CWZ + idx] = (c < 10) ? gWz[r * 10 + c] : (c == 10 ? gbz[r] : 0.0f);
    }
    for (int idx = tid; idx < 3 * 8; idx += nt) {
        int r = idx / 8, c = idx % 8;
        float v = 0.0f;
        if (c < 3) v = gA[r * 3 + c];
        else if (c < 6) v = gBm[r * 3 + (c - 3)];
        g_stage[CPHYS + idx] = v;
    }
    for (int idx = tid; idx < 4; idx += nt)
        g_stage[CB2 + idx] = gb2[idx];
    for (int idx = tid; idx < 96 * 8; idx += nt) {
        int r = idx / 8, c = idx % 8;
        g_stage[CWB + idx] = (c < 6) ? gWb1[r * 6 + c] : (c == 6 ? gbb1[r] : gWb2[r]);
    }
    for (int idx = tid; idx < 3 * 4; idx += nt) {
        int r = idx / 4, c = idx % 4;
        g_stage[CCD + idx] = (c < 3) ? gC[r * 3 + c] : gbb2[r];
    }
}

// ============================================================================
// Fused compute kernel: even blocks -> next_state, odd blocks -> y
// ============================================================================
__global__ void __launch_bounds__(NTHREADS, 6)
fused_kernel(const float* __restrict__ state,
             const float* __restrict__ u,
             float* __restrict__ out_state,
             float* __restrict__ out_y,
             int T)   // T = B/4 for both paths
{
    if ((blockIdx.x & 1) == 0) {
        // ====================================================================
        // STATE path: 4 rows/thread
        // ====================================================================
        int t = (blockIdx.x >> 1) * NTHREADS + threadIdx.x;
        if (t >= T) return;
        int rr[4] = {t, t + T, t + 2 * T, t + 3 * T};

        u64 sp[4][5];
        #pragma unroll
        for (int r = 0; r < 4; r++) {
            const float* s = state + (size_t)rr[r] * TOT;
            const float* up = u + (size_t)rr[r] * IDIM;
            sp[r][0] = pack2(__ldg(s + 0), __ldg(s + 1));
            sp[r][1] = pack2(__ldg(s + 2), __ldg(s + 3));
            sp[r][2] = pack2(__ldg(s + 4), __ldg(s + 5));
            sp[r][3] = pack2(__ldg(s + 6), __ldg(up + 0));
            sp[r][4] = pack2(__ldg(up + 1), __ldg(up + 2));
        }

        // Phase 1: physics cand + gate rows 0..2 + store
        {
            u64 pm[4];
            #pragma unroll
            for (int r = 0; r < 4; r++)
                pm[r] = pack2(getlo(sp[r][1]), gethi(sp[r][3]));  // (s2, u0)
            #pragma unroll
            for (int i = 0; i < SDIM; i++) {
                ulonglong2 phA = CQUAD(CPHYS + i * 8 + 0);  // (a0,a1),(a2,bm0)
                ulonglong2 phB = CQUAD(CPHYS + i * 8 + 4);  // (bm1,bm2),(0,0)
                ulonglong2 zA = CQUAD(CWZ + i * 12 + 0);    // (w0,w1),(w2,w3)
                ulonglong2 zB = CQUAD(CWZ + i * 12 + 4);    // (w4,w5),(w6,w7)
                ulonglong2 zC = CQUAD(CWZ + i * 12 + 8);    // (w8,w9),(bz,0)
                #pragma unroll
                for (int r = 0; r < 4; r++) {
                    u64 d = ffma2(phB.x, sp[r][4], 0ull);
                    d = ffma2(phA.y, pm[r], d);
                    d = ffma2(phA.x, sp[r][0], d);
                    float si = (i == 0) ? getlo(sp[r][0])
                             : (i == 1) ? gethi(sp[r][0]) : getlo(sp[r][1]);
                    float c = fmaf(DT_F, hsum(d), si);
                    u64 g = zC.y;
                    g = ffma2(zA.x, sp[r][0], g);
                    g = ffma2(zA.y, sp[r][1], g);
                    g = ffma2(zB.x, sp[r][2], g);
                    g = ffma2(zB.y, sp[r][3], g);
                    g = ffma2(zC.x, sp[r][4], g);
                    float z = fmaf(0.5f, fast_tanh(0.5f * hsum(g)), 0.5f);
                    out_state[(size_t)rr[r] * TOT + i] = fmaf(z, c - si, si);
                }
            }
        }

        // Phase 2: latent MLP with paired accumulators
        u64 acc01[4], acc23[4];
        {
            ulonglong2 b2q = CQUAD(CB2);   // (b2_0,b2_1),(b2_2,b2_3)
            #pragma unroll
            for (int r = 0; r < 4; r++) { acc01[r] = b2q.x; acc23[r] = b2q.y; }
            #pragma unroll 4
            for (int j = 0; j < HIDL; j++) {
                ulonglong2 wA = CQUAD(CW1 + j * 12 + 0);  // (w0,w1),(w2,w3)
                ulonglong2 wB = CQUAD(CW1 + j * 12 + 4);  // (w4,w5),(w6,w7)
                ulonglong2 wC = CQUAD(CW1 + j * 12 + 8);  // (w8,w9),(b1,0)
                ulonglong2 ww = CQUAD(CW2Q + j * 4);      // (W2_0,W2_1),(W2_2,W2_3)
                u64 t0 = wC.y, t1 = wC.y, t2 = wC.y, t3 = wC.y;
                t0 = ffma2(wA.x, sp[0][0], t0);  t1 = ffma2(wA.x, sp[1][0], t1);
                t2 = ffma2(wA.x, sp[2][0], t2);  t3 = ffma2(wA.x, sp[3][0], t3);
                t0 = ffma2(wA.y, sp[0][1], t0);  t1 = ffma2(wA.y, sp[1][1], t1);
                t2 = ffma2(wA.y, sp[2][1], t2);  t3 = ffma2(wA.y, sp[3][1], t3);
                t0 = ffma2(wB.x, sp[0][2], t0);  t1 = ffma2(wB.x, sp[1][2], t1);
                t2 = ffma2(wB.x, sp[2][2], t2);  t3 = ffma2(wB.x, sp[3][2], t3);
                t0 = ffma2(wB.y, sp[0][3], t0);  t1 = ffma2(wB.y, sp[1][3], t1);
                t2 = ffma2(wB.y, sp[2][3], t2);  t3 = ffma2(wB.y, sp[3][3], t3);
                t0 = ffma2(wC.x, sp[0][4], t0);  t1 = ffma2(wC.x, sp[1][4], t1);
                t2 = ffma2(wC.x, sp[2][4], t2);  t3 = ffma2(wC.x, sp[3][4], t3);
                float h0 = fast_tanh(hsum(t0));
                float h1 = fast_tanh(hsum(t1));
                float h2 = fast_tanh(hsum(t2));
                float h3 = fast_tanh(hsum(t3));
                u64 hh0 = pack2(h0, h0), hh1 = pack2(h1, h1);
                u64 hh2 = pack2(h2, h2), hh3 = pack2(h3, h3);
                acc01[0] = ffma2(ww.x, hh0, acc01[0]);  acc23[0] = ffma2(ww.y, hh0, acc23[0]);
                acc01[1] = ffma2(ww.x, hh1, acc01[1]);  acc23[1] = ffma2(ww.y, hh1, acc23[1]);
                acc01[2] = ffma2(ww.x, hh2, acc01[2]);  acc23[2] = ffma2(ww.y, hh2, acc23[2]);
                acc01[3] = ffma2(ww.x, hh3, acc01[3]);  acc23[3] = ffma2(ww.y, hh3, acc23[3]);
            }
        }

        // Phase 3: gate rows 3..6 + store
        {
            #pragma unroll
            for (int o = 0; o < LDIM; o++) {
                int i = SDIM + o;
                ulonglong2 zA = CQUAD(CWZ + i * 12 + 0);
                ulonglong2 zB = CQUAD(CWZ + i * 12 + 4);
                ulonglong2 zC = CQUAD(CWZ + i * 12 + 8);
                #pragma unroll
                for (int r = 0; r < 4; r++) {
                    float lat = (o == 0) ? gethi(sp[r][1])
                              : (o == 1) ? getlo(sp[r][2])
                              : (o == 2) ? gethi(sp[r][2]) : getlo(sp[r][3]);
                    float dot = (o == 0) ? getlo(acc01[r])
                              : (o == 1) ? gethi(acc01[r])
                              : (o == 2) ? getlo(acc23[r]) : gethi(acc23[r]);
                    float c = fmaf(DT_F, dot, lat);
                    u64 g = zC.y;
                    g = ffma2(zA.x, sp[r][0], g);
                    g = ffma2(zA.y, sp[r][1], g);
                    g = ffma2(zB.x, sp[r][2], g);
                    g = ffma2(zB.y, sp[r][3], g);
                    g = ffma2(zC.x, sp[r][4], g);
                    float z = fmaf(0.5f, fast_tanh(0.5f * hsum(g)), 0.5f);
                    out_state[(size_t)rr[r] * TOT + i] = fmaf(z, c - lat, lat);
                }
            }
        }
    } else {
        // ====================================================================
        // Y path: 4 rows/thread, within-row pairing
        // ====================================================================
        int t = (blockIdx.x >> 1) * NTHREADS + threadIdx.x;
        if (t >= T) return;
        int rr[4] = {t, t + T, t + 2 * T, t + 3 * T};

        // bp[r]: (s0,s1), (s2,u0), (u1,u2)
        u64 bp[4][3];
        u64 s2one[4];
        #pragma unroll
        for (int r = 0; r < 4; r++) {
            const float* s = state + (size_t)rr[r] * TOT;
            const float* up = u + (size_t)rr[r] * IDIM;
            bp[r][0] = pack2(__ldg(s + 0), __ldg(s + 1));
            bp[r][1] = pack2(__ldg(s + 2), __ldg(up + 0));
            bp[r][2] = pack2(__ldg(up + 1), __ldg(up + 2));
            s2one[r] = pack2(getlo(bp[r][1]), 1.0f);   // (s2, 1)
        }

        #pragma unroll
        for (int k = 0; k < SDIM; k++) {
            ulonglong2 cc = CQUAD(CCD + k * 4);   // (c0,c1),(c2,bb2)
            float res[4];
            #pragma unroll
            for (int r = 0; r < 4; r++)
                res[r] = hsum(ffma2(cc.y, s2one[r], ffma2(cc.x, bp[r][0], 0ull)));
            #pragma unroll 4
            for (int j = 0; j < HIDB; j++) {
                int row = k * HIDB + j;
                ulonglong2 wA = CQUAD(CWB + row * 8 + 0);  // (w0,w1),(w2,w3)
                ulonglong2 wB = CQUAD(CWB + row * 8 + 4);  // (w4,w5),(bb1,wb2)
                u64 tinit = pack2(getlo(wB.y), 0.0f);
                float wb2 = gethi(wB.y);
                u64 t0 = ffma2(wA.x, bp[0][0], tinit);
                u64 t1 = ffma2(wA.x, bp[1][0], tinit);
                u64 t2 = ffma2(wA.x, bp[2][0], tinit);
                u64 t3 = ffma2(wA.x, bp[3][0], tinit);
                t0 = ffma2(wA.y, bp[0][1], t0);
                t1 = ffma2(wA.y, bp[1][1], t1);
                t2 = ffma2(wA.y, bp[2][1], t2);
                t3 = ffma2(wA.y, bp[3][1], t3);
                t0 = ffma2(wB.x, bp[0][2], t0);
                t1 = ffma2(wB.x, bp[1][2], t1);
                t2 = ffma2(wB.x, bp[2][2], t2);
                t3 = ffma2(wB.x, bp[3][2], t3);
                res[0] = fmaf(wb2, fast_tanh(hsum(t0)), res[0]);
                res[1] = fmaf(wb2, fast_tanh(hsum(t1)), res[1]);
                res[2] = fmaf(wb2, fast_tanh(hsum(t2)), res[2]);
                res[3] = fmaf(wb2, fast_tanh(hsum(t3)), res[3]);
            }
            #pragma unroll
            for (int r = 0; r < 4; r++)
                out_y[(size_t)rr[r] * SDIM + k] = res[r];
        }
    }
}

extern "C" void kernel_launch(void* const* d_in, const int* in_sizes, int n_in,
                              void* d_out, int out_size) {
    const float* state = (const float*)d_in[0];
    const float* u     = (const float*)d_in[1];
    const float* A     = (const float*)d_in[2];
    const float* Bm    = (const float*)d_in[3];
    const float* C     = (const float*)d_in[4];
    const float* Wz    = (const float*)d_in[5];
    const float* bz    = (const float*)d_in[6];
    const float* W1    = (const float*)d_in[7];
    const float* b1    = (const float*)d_in[8];
    const float* W2    = (const float*)d_in[9];
    const float* b2    = (const float*)d_in[10];
    const float* Wb1   = (const float*)d_in[11];
    const float* bb1   = (const float*)d_in[12];
    const float* Wb2   = (const float*)d_in[13];
    const float* bb2   = (const float*)d_in[14];

    int B = in_sizes[0] / TOT;
    float* out       = (float*)d_out;
    float* out_state = out;                      // [B, 7]
    float* out_y     = out + (size_t)B * TOT;    // [B, 3]

    // 1) pack weights into staging, 2) memcpy D2D into __constant__
    pack_weights<<<8, 256>>>(A, Bm, C, Wz, bz, W1, b1, W2, b2,
                             Wb1, bb1, Wb2, bb2);
    void* cw_addr = nullptr;
    void* st_addr = nullptr;
    cudaGetSymbolAddress(&cw_addr, cw);
    cudaGetSymbolAddress(&st_addr, g_stage);
    cudaMemcpyAsync(cw_addr, st_addr, CW_TOTAL * sizeof(float),
                    cudaMemcpyDeviceToDevice);

    // 3) fused compute
    int T = B / 4;
    int blocks_per_path = (T + NTHREADS - 1) / NTHREADS;
    int grid = blocks_per_path * 2;
    fused_kernel<<<grid, NTHREADS>>>(state, u, out_state, out_y, T);
}